// round 5
// baseline (speedup 1.0000x reference)
#include <cuda_runtime.h>
#include <cstdint>

// x[32768,2048] fp32, bank[20,2048] fp32 -> out[32768,2048] fp32
constexpr int FEA      = 2048;
constexpr int NBANK    = 20;
constexpr int NJP      = NBANK / 2;        // 10 packed bank-pairs
constexpr int RPW      = 4;                // rows per warp-pair
constexpr int NWARP    = 16;               // warps 0-7: K-half 0, 8-15: K-half 1
constexpr int NPAIR    = 8;
constexpr int RPB      = RPW * NPAIR;      // 32 rows per CTA tile
constexpr int NTHREADS = 512;
constexpr int HALF     = FEA / 2;          // 1024 cols per warp
constexpr int KC       = 64;               // cols per chunk (lane owns 2)
constexpr int NCHUNK   = HALF / KC;        // 16 chunks per warp per tile
constexpr int DEPTH    = 3;
constexpr float LAMBDA = 0.0025f;

constexpr int BANK_U64     = NJP * FEA;                        // 163840 B
constexpr int XSTAGE_BYTES = RPW * KC * 4;                     // 1024 B
constexpr int XRING_BYTES  = NWARP * DEPTH * XSTAGE_BYTES;     // 49152 B
constexpr int PART_BYTES   = NWARP * RPW * NJP * 8;            // 5120 B
constexpr int SMEM_BYTES   = BANK_U64 * 8 + XRING_BYTES + PART_BYTES; // 218112

typedef unsigned long long u64;

__device__ __forceinline__ u64 ffma2(u64 a, u64 b, u64 c) {
    u64 d;
    asm("fma.rn.f32x2 %0, %1, %2, %3;" : "=l"(d) : "l"(a), "l"(b), "l"(c));
    return d;
}
__device__ __forceinline__ u64 add2(u64 a, u64 b) {
    u64 d;
    asm("add.rn.f32x2 %0, %1, %2;" : "=l"(d) : "l"(a), "l"(b));
    return d;
}
__device__ __forceinline__ u64 pack2(float lo, float hi) {
    u64 d;
    asm("mov.b64 %0, {%1, %2};" : "=l"(d) : "f"(lo), "f"(hi));
    return d;
}
__device__ __forceinline__ void unpack2(u64 v, float& lo, float& hi) {
    asm("mov.b64 {%0, %1}, %2;" : "=f"(lo), "=f"(hi) : "l"(v));
}
__device__ __forceinline__ float tanh_fast(float v) {
    float r;
    asm("tanh.approx.f32 %0, %1;" : "=f"(r) : "f"(v));
    return r;
}
__device__ __forceinline__ void cp8(uint32_t dst, const float* src) {
    asm volatile("cp.async.ca.shared.global [%0], [%1], 8;\n"
                 :: "r"(dst), "l"(src));
}

extern __shared__ u64 smem_u64[];

__global__ __launch_bounds__(NTHREADS, 1)
void memunit_fused(const float* __restrict__ x,
                   const float* __restrict__ bank,
                   float* __restrict__ out,
                   int n_tiles)
{
    u64*  s_pair = smem_u64;                                 // [NJP][FEA]
    char* s_x    = (char*)(smem_u64 + BANK_U64);             // per-warp ring
    u64*  s_part = (u64*)(s_x + XRING_BYTES);                // [NWARP][RPW][NJP]

    const int tid  = threadIdx.x;
    const int warp = tid >> 5;
    const int lane = tid & 31;
    const int half = warp >> 3;          // K-half owned by this warp
    const int p    = warp & 7;           // row-pair index within tile
    const int G    = gridDim.x;

    // j-pair-interleaved bank (no swizzle needed: all accesses contiguous)
    for (int idx = tid; idx < BANK_U64; idx += NTHREADS) {
        const int jp = idx >> 11;
        const int k  = idx & (FEA - 1);
        s_pair[idx] = pack2(bank[(2 * jp) * FEA + k],
                            bank[(2 * jp + 1) * FEA + k]);
    }
    __syncthreads();

    const int my_tiles = (n_tiles - (int)blockIdx.x + G - 1) / G;
    const uint32_t xs0 =
        (uint32_t)__cvta_generic_to_shared(s_x) +
        (uint32_t)(warp * (DEPTH * XSTAGE_BYTES) + lane * 8);
    const char* xwarp = s_x + warp * (DEPTH * XSTAGE_BYTES);
    const int kbase = half * HALF;       // this warp's first column

    // issue chunk g (flattened over tiles*chunks) into ring slot
    auto issue = [&](int g, int slot) {
        const int t2 = g >> 4;           // g / NCHUNK
        if (t2 < my_tiles) {
            const int kc2 = g & (NCHUNK - 1);
            const float* src =
                x + ((long)((int)blockIdx.x + t2 * G) * RPB + p * RPW) * FEA
                  + kbase + kc2 * KC + 2 * lane;
            const uint32_t dst = xs0 + slot * XSTAGE_BYTES;
            #pragma unroll
            for (int r = 0; r < RPW; r++)
                cp8(dst + r * 256, src + r * FEA);
        }
        asm volatile("cp.async.commit_group;\n" ::: "memory");
    };

    #pragma unroll
    for (int s = 0; s < DEPTH; s++) issue(s, s);

    int f = 0, slot = 0;

    for (int t = 0; t < my_tiles; t++) {
        const long row0 = (long)((int)blockIdx.x + t * G) * RPB + p * RPW;

        // ============ GEMM1 (this warp's K-half): packed dots ==============
        u64 acc[RPW][NJP];
        #pragma unroll
        for (int r = 0; r < RPW; r++)
            #pragma unroll
            for (int jp = 0; jp < NJP; jp++) acc[r][jp] = 0ull;

        #pragma unroll 1
        for (int kc = 0; kc < NCHUNK; kc++) {
            asm volatile("cp.async.wait_group 2;\n" ::: "memory");

            const char* xst = xwarp + slot * XSTAGE_BYTES;
            float2 xv[RPW];
            #pragma unroll
            for (int r = 0; r < RPW; r++)
                xv[r] = *reinterpret_cast<const float2*>(xst + r * 256 + lane * 8);

            issue(f + DEPTH, slot);

            u64 px0[RPW], px1[RPW];
            #pragma unroll
            for (int r = 0; r < RPW; r++) {
                px0[r] = pack2(xv[r].x, xv[r].x);
                px1[r] = pack2(xv[r].y, xv[r].y);
            }

            const int kb = kbase + kc * KC + 2 * lane;   // u64 col index
            #pragma unroll
            for (int jp = 0; jp < NJP; jp++) {
                const ulonglong2 b =
                    *reinterpret_cast<const ulonglong2*>(s_pair + jp * FEA + kb);
                #pragma unroll
                for (int r = 0; r < RPW; r++) {
                    acc[r][jp] = ffma2(px0[r], b.x, acc[r][jp]);
                    acc[r][jp] = ffma2(px1[r], b.y, acc[r][jp]);
                }
            }

            f++;
            slot++; if (slot == DEPTH) slot = 0;
        }

        // ---- butterfly reduce within warp (packed adds) -------------------
        #pragma unroll
        for (int r = 0; r < RPW; r++)
            #pragma unroll
            for (int jp = 0; jp < NJP; jp++) {
                u64 v = acc[r][jp];
                v = add2(v, __shfl_xor_sync(0xffffffffu, v, 16));
                v = add2(v, __shfl_xor_sync(0xffffffffu, v, 8));
                v = add2(v, __shfl_xor_sync(0xffffffffu, v, 4));
                v = add2(v, __shfl_xor_sync(0xffffffffu, v, 2));
                v = add2(v, __shfl_xor_sync(0xffffffffu, v, 1));
                acc[r][jp] = v;
            }

        // ---- combine the two K-halves via SMEM exchange -------------------
        if (lane == 0) {
            u64* dst = s_part + (warp * RPW) * NJP;
            #pragma unroll
            for (int r = 0; r < RPW; r++)
                #pragma unroll
                for (int jp = 0; jp < NJP; jp++)
                    dst[r * NJP + jp] = acc[r][jp];
        }
        __syncthreads();
        {
            const u64* src = s_part + ((warp ^ 8) * RPW) * NJP;  // partner
            #pragma unroll
            for (int r = 0; r < RPW; r++)
                #pragma unroll
                for (int jp = 0; jp < NJP; jp++)
                    acc[r][jp] = add2(acc[r][jp], src[r * NJP + jp]);
        }
        __syncthreads();   // protect s_part before next tile's writes

        // ---- softmax -> softshrink -> softmax, repack into acc ------------
        #pragma unroll
        for (int r = 0; r < RPW; r++) {
            float att[NBANK];
            #pragma unroll
            for (int jp = 0; jp < NJP; jp++)
                unpack2(acc[r][jp], att[2 * jp], att[2 * jp + 1]);

            float m = att[0];
            #pragma unroll
            for (int j = 1; j < NBANK; j++) m = fmaxf(m, att[j]);

            float s = 0.f;
            #pragma unroll
            for (int j = 0; j < NBANK; j++) {
                const float e = __expf(att[j] - m);
                att[j] = e;
                s += e;
            }
            const float inv = 1.0f / s;

            float m2 = 0.f;   // att >= 0 => softshrink = max(att - lambda, 0)
            #pragma unroll
            for (int j = 0; j < NBANK; j++) {
                const float a = fmaxf(att[j] * inv - LAMBDA, 0.f);
                att[j] = a;
                m2 = fmaxf(m2, a);
            }

            float s2 = 0.f;
            #pragma unroll
            for (int j = 0; j < NBANK; j++) {
                const float e = __expf(att[j] - m2);
                att[j] = e;
                s2 += e;
            }
            const float inv2 = 1.0f / s2;
            #pragma unroll
            for (int jp = 0; jp < NJP; jp++)
                acc[r][jp] = pack2(att[2 * jp] * inv2, att[2 * jp + 1] * inv2);
        }

        // ============ GEMM2 + tanh on this warp's K-half ===================
        float* op = out + row0 * FEA + kbase + 2 * lane;
        #pragma unroll 1
        for (int cc = 0; cc < NCHUNK; cc++) {
            const int kb = kbase + cc * KC + 2 * lane;
            u64 o0[RPW], o1[RPW];
            #pragma unroll
            for (int r = 0; r < RPW; r++) { o0[r] = 0ull; o1[r] = 0ull; }

            #pragma unroll
            for (int jp = 0; jp < NJP; jp++) {
                const ulonglong2 b =
                    *reinterpret_cast<const ulonglong2*>(s_pair + jp * FEA + kb);
                #pragma unroll
                for (int r = 0; r < RPW; r++) {
                    o0[r] = ffma2(acc[r][jp], b.x, o0[r]);
                    o1[r] = ffma2(acc[r][jp], b.y, o1[r]);
                }
            }

            #pragma unroll
            for (int r = 0; r < RPW; r++) {
                float l0, h0, l1, h1;
                unpack2(o0[r], l0, h0);
                unpack2(o1[r], l1, h1);
                float2 v;
                v.x = tanh_fast(l0 + h0);
                v.y = tanh_fast(l1 + h1);
                *reinterpret_cast<float2*>(op + r * FEA + cc * KC) = v;
            }
        }
    }
}

extern "C" void kernel_launch(void* const* d_in, const int* in_sizes, int n_in,
                              void* d_out, int out_size)
{
    const float* x    = reinterpret_cast<const float*>(d_in[0]);
    const float* bank = reinterpret_cast<const float*>(d_in[1]);
    float* out        = reinterpret_cast<float*>(d_out);

    const int rows    = in_sizes[0] / FEA;   // 32768
    const int n_tiles = rows / RPB;          // 1024

    cudaFuncSetAttribute(memunit_fused,
                         cudaFuncAttributeMaxDynamicSharedMemorySize, SMEM_BYTES);

    int dev = 0, sms = 148;
    cudaGetDevice(&dev);
    cudaDeviceGetAttribute(&sms, cudaDevAttrMultiProcessorCount, dev);

    int grid = (sms < n_tiles) ? sms : n_tiles;
    memunit_fused<<<grid, NTHREADS, SMEM_BYTES>>>(x, bank, out, n_tiles);
}

// round 7
// speedup vs baseline: 1.4441x; 1.4441x over previous
#include <cuda_runtime.h>
#include <cuda_fp16.h>
#include <cstdint>

// x[32768,2048] fp32, bank[20,2048] fp32 -> out[32768,2048] fp32
constexpr int FEA    = 2048;
constexpr int NBANK  = 20;
constexpr int TILE_M = 32;             // rows per tile (1024 tiles)
constexpr int CHUNK  = 256;            // x cols per chunk
constexpr int NCH    = FEA / CHUNK;    // 8
constexpr float LAMBDA = 0.0025f;

// SMEM map
constexpr int SM_BANK  = 0;                        // [32 j][2048 k] fp16, swizzled
constexpr int BANKB    = 32 * FEA * 2;             // 131072
constexpr int SM_X     = BANKB;                    // x ring: 2 x 16KB
constexpr int XSLOTB   = TILE_M * CHUNK * 2;       // 16384
constexpr int SM_LOGIT = SM_X + 2 * XSLOTB;        // 163840: [32][32] f32
constexpr int SM_ATT   = SM_LOGIT + 32 * 32 * 4;   // 167936: [32][32] fp16
constexpr int SM_TOTAL = SM_ATT + 32 * 32 * 2;     // 169984

__device__ __forceinline__ uint32_t s2u(const void* p) {
    uint32_t a;
    asm("{ .reg .u64 t; cvta.to.shared.u64 t, %1; cvt.u32.u64 %0, t; }"
        : "=r"(a) : "l"(p));
    return a;
}
__device__ __forceinline__ void ldsm4(uint32_t a, uint32_t& r0, uint32_t& r1,
                                      uint32_t& r2, uint32_t& r3) {
    asm volatile("ldmatrix.sync.aligned.m8n8.x4.shared.b16 {%0,%1,%2,%3}, [%4];"
                 : "=r"(r0), "=r"(r1), "=r"(r2), "=r"(r3) : "r"(a));
}
__device__ __forceinline__ void ldsm2(uint32_t a, uint32_t& r0, uint32_t& r1) {
    asm volatile("ldmatrix.sync.aligned.m8n8.x2.shared.b16 {%0,%1}, [%2];"
                 : "=r"(r0), "=r"(r1) : "r"(a));
}
__device__ __forceinline__ void ldsm2t(uint32_t a, uint32_t& r0, uint32_t& r1) {
    asm volatile("ldmatrix.sync.aligned.m8n8.x2.trans.shared.b16 {%0,%1}, [%2];"
                 : "=r"(r0), "=r"(r1) : "r"(a));
}
__device__ __forceinline__ void mma16816(float& d0, float& d1, float& d2, float& d3,
                                         uint32_t a0, uint32_t a1, uint32_t a2, uint32_t a3,
                                         uint32_t b0, uint32_t b1) {
    asm volatile(
        "mma.sync.aligned.m16n8k16.row.col.f32.f16.f16.f32 "
        "{%0,%1,%2,%3}, {%4,%5,%6,%7}, {%8,%9}, {%0,%1,%2,%3};"
        : "+f"(d0), "+f"(d1), "+f"(d2), "+f"(d3)
        : "r"(a0), "r"(a1), "r"(a2), "r"(a3), "r"(b0), "r"(b1));
}
__device__ __forceinline__ float tanh_fast(float v) {
    float r;
    asm("tanh.approx.f32 %0, %1;" : "=f"(r) : "f"(v));
    return r;
}
__device__ __forceinline__ uint32_t h2bits(__half2 h) {
    return *reinterpret_cast<uint32_t*>(&h);
}

extern __shared__ char smc[];

__global__ void __launch_bounds__(256, 1)
memunit_hmma(const float* __restrict__ x,
             const float* __restrict__ bank,
             float* __restrict__ out,
             int n_tiles)
{
    const uint32_t sbase = s2u(smc);
    const int tid  = threadIdx.x;
    const int warp = tid >> 5;
    const int lane = tid & 31;

    // ---- bank -> fp16 [32 j pad][2048], swizzle: byte = j*4096 + (2k ^ ((j&7)<<4))
    for (int idx = tid; idx < 32 * FEA; idx += 256) {
        const int j = idx >> 11, k = idx & (FEA - 1);
        const float v = (j < NBANK) ? bank[j * FEA + k] : 0.f;
        *reinterpret_cast<__half*>(smc + SM_BANK + j * 4096 + ((2 * k) ^ ((j & 7) << 4)))
            = __float2half(v);
    }
    __syncthreads();

    const int mh = warp >> 2;              // m-half (0/1): rows mh*16..+15
    const int nt = warp & 3;               // GEMM1 n-tile / GEMM2 n-quarter

    // ldmatrix A address components (row-major, x4 pattern)
    const int arow = mh * 16 + (lane & 7) + ((lane & 8) ? 8 : 0);
    const int akb  = (lane & 16) ? 16 : 0;             // byte offset of k+8
    const int asw  = (arow & 7) << 4;
    // GEMM1 B (non-trans x2): rows j = nt*8 + (lane&7)
    const int brow = nt * 8 + (lane & 7);
    const int bkb  = (lane & 8) ? 16 : 0;
    const int bsw  = (brow & 7) << 4;
    // GEMM2 B (trans x2): rows j = ks*16 + jrow0
    const int jrow0 = (lane & 7) + ((lane & 8) ? 8 : 0);
    const int sw2   = (jrow0 & 7) << 4;
    // D / logit / output row mapping
    const int lr = mh * 16 + (lane >> 2);
    const int lc2 = (lane & 3) * 2;

    float4 pf[8];   // x prefetch: 32 f32 per thread (one chunk)

    auto ldx = [&](int tile, int c) {
        const float4* p = reinterpret_cast<const float4*>(x)
                        + (long)tile * TILE_M * (FEA / 4) + c * (CHUNK / 4);
        #pragma unroll
        for (int i = 0; i < 8; i++) {
            const int f = i * 256 + tid;              // float4 idx in chunk
            pf[i] = p[(f >> 6) * (FEA / 4) + (f & 63)];
        }
    };
    auto stx = [&](int slot) {
        char* s = smc + SM_X + slot * XSLOTB;
        #pragma unroll
        for (int i = 0; i < 8; i++) {
            const int f = i * 256 + tid;
            const int row = f >> 6, kb = (f & 63) * 8;
            uint2 pkt;
            pkt.x = h2bits(__floats2half2_rn(pf[i].x, pf[i].y));
            pkt.y = h2bits(__floats2half2_rn(pf[i].z, pf[i].w));
            *reinterpret_cast<uint2*>(s + row * 512 + (kb ^ ((row & 7) << 4))) = pkt;
        }
    };

    const int G = gridDim.x;
    int tile = blockIdx.x;
    if (tile < n_tiles) ldx(tile, 0);

    for (; tile < n_tiles; tile += G) {
        const long row0 = (long)tile * TILE_M;

        // ============ GEMM1: logits[32 x 32] via HMMA =======================
        float d0 = 0.f, d1 = 0.f, d2 = 0.f, d3 = 0.f;
        #pragma unroll 1
        for (int c = 0; c < NCH; c++) {
            stx(c & 1);
            if (c + 1 < NCH) ldx(tile, c + 1);
            else             ldx((tile + G < n_tiles) ? tile + G : tile, 0);
            __syncthreads();

            const uint32_t xs = sbase + SM_X + (c & 1) * XSLOTB + arow * 512;
            const uint32_t bb = sbase + SM_BANK + brow * 4096;
            #pragma unroll
            for (int ks = 0; ks < 16; ks++) {
                uint32_t a0, a1, a2, a3, b0, b1;
                ldsm4(xs + ((ks * 32 + akb) ^ asw), a0, a1, a2, a3);
                ldsm2(bb + ((c * 512 + ks * 32 + bkb) ^ bsw), b0, b1);
                mma16816(d0, d1, d2, d3, a0, a1, a2, a3, b0, b1);
            }
            __syncthreads();
        }

        // ============ logits -> SMEM ========================================
        float* lg = reinterpret_cast<float*>(smc + SM_LOGIT);
        *reinterpret_cast<float2*>(&lg[lr * 32 + nt * 8 + lc2])       = make_float2(d0, d1);
        *reinterpret_cast<float2*>(&lg[(lr + 8) * 32 + nt * 8 + lc2]) = make_float2(d2, d3);
        __syncthreads();

        // ============ softmax -> softshrink -> softmax (1 thread / row) =====
        if (tid < 32) {
            float att[NBANK];
            #pragma unroll
            for (int j = 0; j < NBANK; j++) att[j] = lg[tid * 32 + j];

            float m = att[0];
            #pragma unroll
            for (int j = 1; j < NBANK; j++) m = fmaxf(m, att[j]);
            float s = 0.f;
            #pragma unroll
            for (int j = 0; j < NBANK; j++) { float e = __expf(att[j] - m); att[j] = e; s += e; }
            const float inv = 1.0f / s;

            float m2 = 0.f;   // att >= 0 => softshrink = max(att - lambda, 0)
            #pragma unroll
            for (int j = 0; j < NBANK; j++) {
                float a = fmaxf(att[j] * inv - LAMBDA, 0.f);
                att[j] = a;
                m2 = fmaxf(m2, a);
            }
            float s2 = 0.f;
            #pragma unroll
            for (int j = 0; j < NBANK; j++) { float e = __expf(att[j] - m2); att[j] = e; s2 += e; }
            const float inv2 = 1.0f / s2;

            __half2* av = reinterpret_cast<__half2*>(smc + SM_ATT + tid * 64);
            #pragma unroll
            for (int jp = 0; jp < 10; jp++)
                av[jp] = __floats2half2_rn(att[2 * jp] * inv2, att[2 * jp + 1] * inv2);
            #pragma unroll
            for (int jp = 10; jp < 16; jp++)
                av[jp] = __floats2half2_rn(0.f, 0.f);
        }
        __syncthreads();

        // ============ GEMM2 + tanh: out[32 x 2048] ==========================
        uint32_t aA0[4], aA1[4];
        {
            const uint32_t ab = sbase + SM_ATT + arow * 64 + ((lane & 16) ? 16 : 0);
            ldsm4(ab,      aA0[0], aA0[1], aA0[2], aA0[3]);   // k = j 0..15
            ldsm4(ab + 32, aA1[0], aA1[1], aA1[2], aA1[3]);   // k = j 16..31
        }
        const uint32_t bt0 = sbase + SM_BANK + jrow0 * 4096;
        const uint32_t bt1 = sbase + SM_BANK + (jrow0 + 16) * 4096;
        float* orow0 = out + (row0 + lr) * FEA + lc2;
        float* orow1 = out + (row0 + lr + 8) * FEA + lc2;

        #pragma unroll 4
        for (int t2 = 0; t2 < 64; t2++) {
            const int nb = (nt * 64 + t2) * 8;
            const int nbyte = (nb * 2) ^ sw2;
            uint32_t b00, b01, b10, b11;
            ldsm2t(bt0 + nbyte, b00, b01);
            ldsm2t(bt1 + nbyte, b10, b11);
            float e0 = 0.f, e1 = 0.f, e2 = 0.f, e3 = 0.f;
            mma16816(e0, e1, e2, e3, aA0[0], aA0[1], aA0[2], aA0[3], b00, b01);
            mma16816(e0, e1, e2, e3, aA1[0], aA1[1], aA1[2], aA1[3], b10, b11);
            *reinterpret_cast<float2*>(orow0 + nb) =
                make_float2(tanh_fast(e0), tanh_fast(e1));
            *reinterpret_cast<float2*>(orow1 + nb) =
                make_float2(tanh_fast(e2), tanh_fast(e3));
        }
        __syncthreads();   // s_att / logits / x-ring safe for next tile
    }
}

extern "C" void kernel_launch(void* const* d_in, const int* in_sizes, int n_in,
                              void* d_out, int out_size)
{
    const float* x    = reinterpret_cast<const float*>(d_in[0]);
    const float* bank = reinterpret_cast<const float*>(d_in[1]);
    float* out        = reinterpret_cast<float*>(d_out);

    const int rows    = in_sizes[0] / FEA;   // 32768
    const int n_tiles = rows / TILE_M;       // 1024

    cudaFuncSetAttribute(memunit_hmma,
                         cudaFuncAttributeMaxDynamicSharedMemorySize, SM_TOTAL);

    int dev = 0, sms = 148;
    cudaGetDevice(&dev);
    cudaDeviceGetAttribute(&sms, cudaDevAttrMultiProcessorCount, dev);

    const int grid = (sms < n_tiles) ? sms : n_tiles;
    memunit_hmma<<<grid, 256, SM_TOTAL>>>(x, bank, out, n_tiles);
}